// round 1
// baseline (speedup 1.0000x reference)
#include <cuda_runtime.h>
#include <math_constants.h>

#define BB 4
#define HH 512
#define WW 512
#define HW (HH*WW)
#define RAD 3
#define NKPT 512
#define CAP 65536
#define NFEAT 128

// Output layout (float32, concatenated in reference tuple order)
#define OFF_SCORE 0
#define OFF_KPTS  (BB*HW)
#define OFF_FEAS  (OFF_KPTS + BB*NKPT*4)
#define OFF_PIX   (OFF_FEAS + BB*NFEAT*NKPT)

// Scratch (static device globals: no allocation allowed)
__device__ float g_score[BB*HW];
__device__ float g_tmpf [BB*HW];
__device__ float g_supp [BB*HW];
__device__ unsigned char g_mask [BB*HW];
__device__ unsigned char g_tmpm [BB*HW];
__device__ unsigned char g_suppm[BB*HW];
__device__ unsigned long long g_cand[BB*CAP];
__device__ int g_count[BB];
__device__ int g_sel[BB*NKPT];

// 1) score = raw * (bev[:,2] > 0); also reset counters; write score2d output
__global__ void k_score(const float* __restrict__ bev,
                        const float* __restrict__ raw,
                        float* __restrict__ out) {
    int p = blockIdx.x * blockDim.x + threadIdx.x;
    if (p >= BB*HW) return;
    int b = p / HW, i = p - b*HW;
    float g = bev[(b*7 + 2)*HW + i] > 0.f ? 1.f : 0.f;
    float s = raw[p] * g;
    g_score[p] = s;
    out[OFF_SCORE + p] = s;
    if (p < BB) g_count[p] = 0;
}

// horizontal 1x7 max over float; src: 0 = g_score, 1 = g_supp; dst = g_tmpf
__global__ void k_hpool_f(int src) {
    int p = blockIdx.x * blockDim.x + threadIdx.x;
    if (p >= BB*HW) return;
    int i = p % HW;
    int x = i % WW;
    const float* in = src ? g_supp : g_score;
    const float* row = in + (p - x);   // start of this row
    float m = -CUDART_INF_F;
    int x0 = x - RAD; if (x0 < 0) x0 = 0;
    int x1 = x + RAD; if (x1 > WW-1) x1 = WW-1;
    #pragma unroll 7
    for (int xx = x0; xx <= x1; ++xx) m = fmaxf(m, row[xx]);
    g_tmpf[p] = m;
}

// vertical 7x1 max of g_tmpf; mask = (max == g_score)
__global__ void k_vpool_eq() {
    int p = blockIdx.x * blockDim.x + threadIdx.x;
    if (p >= BB*HW) return;
    int b = p / HW, i = p - b*HW;
    int y = i / WW, x = i - y*WW;
    float m = -CUDART_INF_F;
    int y0 = y - RAD; if (y0 < 0) y0 = 0;
    int y1 = y + RAD; if (y1 > HH-1) y1 = HH-1;
    const float* base = g_tmpf + b*HW + x;
    #pragma unroll 7
    for (int yy = y0; yy <= y1; ++yy) m = fmaxf(m, base[yy*WW]);
    g_mask[p] = (m == g_score[p]) ? 1 : 0;
}

// horizontal dilation of g_mask -> g_tmpm
__global__ void k_hdil() {
    int p = blockIdx.x * blockDim.x + threadIdx.x;
    if (p >= BB*HW) return;
    int i = p % HW;
    int x = i % WW;
    const unsigned char* row = g_mask + (p - x);
    unsigned char m = 0;
    int x0 = x - RAD; if (x0 < 0) x0 = 0;
    int x1 = x + RAD; if (x1 > WW-1) x1 = WW-1;
    #pragma unroll 7
    for (int xx = x0; xx <= x1; ++xx) m |= row[xx];
    g_tmpm[p] = m;
}

// vertical dilation -> suppm; supp_scores = suppm ? 0 : score
__global__ void k_vdil_supp() {
    int p = blockIdx.x * blockDim.x + threadIdx.x;
    if (p >= BB*HW) return;
    int b = p / HW, i = p - b*HW;
    int y = i / WW, x = i - y*WW;
    unsigned char m = 0;
    int y0 = y - RAD; if (y0 < 0) y0 = 0;
    int y1 = y + RAD; if (y1 > HH-1) y1 = HH-1;
    const unsigned char* base = g_tmpm + b*HW + x;
    #pragma unroll 7
    for (int yy = y0; yy <= y1; ++yy) m |= base[yy*WW];
    g_suppm[p] = m;
    g_supp[p]  = m ? 0.f : g_score[p];
}

// vertical max of g_tmpf (hpooled supp); mask |= (max == supp) & !suppm
__global__ void k_vpool_upd() {
    int p = blockIdx.x * blockDim.x + threadIdx.x;
    if (p >= BB*HW) return;
    int b = p / HW, i = p - b*HW;
    int y = i / WW, x = i - y*WW;
    float m = -CUDART_INF_F;
    int y0 = y - RAD; if (y0 < 0) y0 = 0;
    int y1 = y + RAD; if (y1 > HH-1) y1 = HH-1;
    const float* base = g_tmpf + b*HW + x;
    #pragma unroll 7
    for (int yy = y0; yy <= y1; ++yy) m = fmaxf(m, base[yy*WW]);
    if (m == g_supp[p] && g_suppm[p] == 0) g_mask[p] = 1;
}

// compact candidates: key = (score_bits << 32) | (HW-1-idx)
// '>' on keys == (higher score) or (equal score, lower idx) first — matches lax.top_k ties
__global__ void k_compact() {
    int p = blockIdx.x * blockDim.x + threadIdx.x;
    if (p >= BB*HW) return;
    int b = p / HW, i = p - b*HW;
    float s = g_score[p];
    if (g_mask[p] && s > 0.f) {
        int pos = atomicAdd(&g_count[b], 1);
        if (pos < CAP) {
            unsigned long long key =
                ((unsigned long long)__float_as_uint(s) << 32) |
                (unsigned int)(HW - 1 - i);
            g_cand[b*CAP + pos] = key;
        }
    }
}

// rank selection: one warp per candidate; rank = #keys greater; rank<NKPT -> slot
#define RTILE 2048
__global__ void k_rank() {
    int b = blockIdx.y;
    int n = g_count[b]; if (n > CAP) n = CAP;
    int warpsPerBlock = blockDim.x >> 5;
    if (blockIdx.x * warpsPerBlock >= n) return;
    int wid  = threadIdx.x >> 5;
    int lane = threadIdx.x & 31;
    int cid  = blockIdx.x * warpsPerBlock + wid;
    __shared__ unsigned long long tile[RTILE];
    unsigned long long mykey = (cid < n) ? g_cand[b*CAP + cid] : 0ULL;
    int rank = 0;
    for (int j0 = 0; j0 < n; j0 += RTILE) {
        int m = n - j0; if (m > RTILE) m = RTILE;
        for (int t = threadIdx.x; t < m; t += blockDim.x)
            tile[t] = g_cand[b*CAP + j0 + t];
        __syncthreads();
        if (cid < n) {
            for (int t = lane; t < m; t += 32)
                rank += (tile[t] > mykey) ? 1 : 0;
        }
        __syncthreads();
    }
    #pragma unroll
    for (int off = 16; off; off >>= 1)
        rank += __shfl_down_sync(0xffffffffu, rank, off);
    if (cid < n && lane == 0 && rank < NKPT) {
        int idx = HW - 1 - (int)(mykey & 0xffffffffu);
        g_sel[b*NKPT + rank] = idx;
    }
}

// cold fallback: fewer than NKPT candidates -> fill with smallest non-candidate indices
__global__ void k_fill() {
    int b = blockIdx.x;
    int n = g_count[b];
    if (n >= NKPT) return;
    if (n > CAP) n = CAP;
    int slot = n;
    for (int p = 0; p < HW && slot < NKPT; ++p) {
        bool cand = (g_mask[b*HW + p] != 0) && (g_score[b*HW + p] > 0.f);
        if (!cand) g_sel[b*NKPT + (slot++)] = p;
    }
}

// kpts (b,NKPT,4) and pixels (b,NKPT,2)
__global__ void k_gather_small(const float* __restrict__ bev,
                               float* __restrict__ out) {
    int t = blockIdx.x * blockDim.x + threadIdx.x;
    if (t >= BB*NKPT) return;
    int b = t / NKPT;
    int idx = g_sel[t];
    int u = idx / WW, v = idx - u*WW;
    float* ok = out + OFF_KPTS + t*4;
    ok[0] = bev[(b*7 + 3)*HW + idx];
    ok[1] = bev[(b*7 + 4)*HW + idx];
    ok[2] = 0.f;
    ok[3] = 1.f;
    float* op = out + OFF_PIX + t*2;
    op[0] = (float)u;
    op[1] = (float)v;
}

// feas_kpt (b,NFEAT,NKPT)
__global__ void k_gather_feat(const float* __restrict__ feat,
                              float* __restrict__ out) {
    int t = blockIdx.x * blockDim.x + threadIdx.x;
    if (t >= BB*NFEAT*NKPT) return;
    int k  = t % NKPT;
    int bc = t / NKPT;
    int b  = bc / NFEAT;
    int idx = g_sel[b*NKPT + k];
    out[OFF_FEAS + t] = feat[bc*HW + idx];
}

extern "C" void kernel_launch(void* const* d_in, const int* in_sizes, int n_in,
                              void* d_out, int out_size) {
    const float* bev  = (const float*)d_in[0];
    const float* raw  = (const float*)d_in[1];
    const float* feat = (const float*)d_in[2];
    float* out = (float*)d_out;

    const int TB = 256;
    const int NBLK = (BB*HW + TB - 1) / TB;

    k_score<<<NBLK, TB>>>(bev, raw, out);

    // initial max_mask
    k_hpool_f<<<NBLK, TB>>>(0);
    k_vpool_eq<<<NBLK, TB>>>();

    // 2 NMS iterations
    for (int it = 0; it < 2; ++it) {
        k_hdil<<<NBLK, TB>>>();
        k_vdil_supp<<<NBLK, TB>>>();
        k_hpool_f<<<NBLK, TB>>>(1);
        k_vpool_upd<<<NBLK, TB>>>();
    }

    k_compact<<<NBLK, TB>>>();

    dim3 rgrid((CAP + 31) / 32, BB);
    k_rank<<<rgrid, 1024>>>();
    k_fill<<<BB, 1>>>();

    k_gather_small<<<(BB*NKPT + TB - 1)/TB, TB>>>(bev, out);
    k_gather_feat<<<(BB*NFEAT*NKPT + TB - 1)/TB, TB>>>(feat, out);
}